// round 2
// baseline (speedup 1.0000x reference)
#include <cuda_runtime.h>
#include <cuda_fp16.h>

// ---------------------------------------------------------------- constants
#define A_TOT 900
#define P_PTS 13
#define NCAMS 6
#define CDIM  256
#define NPN   (P_PTS * NCAMS)        // 78 (p-major, cam inner)

// level shapes
#define W0 176
#define H0 64
#define W1 88
#define H1 32
#define W2 44
#define H2 16
#define W3 22
#define H3 8

// fm1 fp16 scratch: 6*32*88*256 halves = 4,325,376 -> as uint2 (4 halves): 1,081,344
#define FM1_U2 1081344
#define CONV_BLKS (FM1_U2 / 256)     // 4224 exactly

// daf_small decomposition
#define L2_CHUNK 113                  // anchors per level-2 block (8 chunks)
#define L2_NCHUNK 8
#define NB2 (NCAMS * 4 * L2_NCHUNK)   // 192 blocks (cam, ch-quarter, chunk)
#define L3_CHUNK 36                   // 25 chunks exactly
#define L3_NCHUNK 25
#define NB3 (NCAMS * L3_NCHUNK)       // 150 blocks

// daf_small dynamic smem layout (floats):
//   tile:   45056 floats (180224 B)   [704px x 64ch  |  176px x 256ch]
//   s_off:  ushort4[1470]  at float offset 45056  (11760 B)
//   s_w:    float4 [1469]  at float offset 45056+2940=47996 (byte 191984, 16-aligned)
#define SM_TILE_F   45056
#define SM_OFF_F    45056
#define SM_W_F      (45056 + 2940)
#define SMEM_SMALL  215488

__device__ float g_acc[A_TOT * CDIM];               // level 0+1 accum
__device__ uint2 g_fm1h[FM1_U2];                    // fm1 as fp16
__device__ float g_part2[NCAMS * A_TOT * CDIM];     // level-2 per-cam partials
__device__ float g_part3[NCAMS * A_TOT * CDIM];     // level-3 per-cam partials

// ---------------------------------------------------------------------------
// K1: fused prep. Blocks [0, CONV_BLKS): convert fm1 to fp16.
//     Blocks [CONV_BLKS, CONV_BLKS+900): init out (bias + instance concat).
// ---------------------------------------------------------------------------
__global__ void __launch_bounds__(256) prep_kernel(
    const float* __restrict__ fm1, const float* __restrict__ inst,
    const float* __restrict__ bproj, float* __restrict__ out)
{
    int b = blockIdx.x;
    int t = threadIdx.x;
    if (b < CONV_BLKS) {
        int i = b * 256 + t;
        float4 f = __ldg(((const float4*)fm1) + i);
        __half2 h0 = __floats2half2_rn(f.x, f.y);
        __half2 h1 = __floats2half2_rn(f.z, f.w);
        uint2 u;
        u.x = *reinterpret_cast<unsigned*>(&h0);
        u.y = *reinterpret_cast<unsigned*>(&h1);
        g_fm1h[i] = u;
    } else {
        int a = b - CONV_BLKS;
        out[(size_t)a * 512 + t]       = __ldg(bproj + t);
        out[(size_t)a * 512 + 256 + t] = __ldg(inst + (size_t)a * 256 + t);
    }
}

// ---------------------------------------------------------------------------
// K2: daf_big — levels 0 (f32 gather) + 1 (fp16 gather). Block = 1 anchor,
// 64 threads, thread t owns channels [4t, 4t+4). Writes g_acc.
// ---------------------------------------------------------------------------
__global__ void __launch_bounds__(64) daf_big_kernel(
    const float* __restrict__ fm0, const float* __restrict__ pts,
    const float* __restrict__ wts)
{
    __shared__ int4   soff0[NPN];
    __shared__ float4 swt0[NPN];
    __shared__ int4   soff1[NPN];
    __shared__ float4 swt1[NPN];
    __shared__ float  swg[NPN * 16];   // [pn][l0 g0..7 | l1 g0..7]

    const int a = blockIdx.x;
    const int t = threadIdx.x;

    // stage group weights for levels 0,1: per pn first 16 floats of the 32-float record
    {
        const float4* wsrc = (const float4*)(wts + (size_t)a * NPN * 32);
        #pragma unroll
        for (int i = t; i < NPN * 4; i += 64) {
            int pn = i >> 2, j = i & 3;
            ((float4*)swg)[i] = __ldg(wsrc + pn * 8 + j);
        }
    }

    // per-sample bilinear data for levels 0,1
    {
        const float* pbase = pts + (size_t)a * NPN * 2;
        for (int s = t; s < NPN * 2; s += 64) {
            int pn = s >> 1, l = s & 1;
            int n = pn % NCAMS;
            float px = __ldg(pbase + pn * 2 + 0);
            float py = __ldg(pbase + pn * 2 + 1);
            int W = l ? W1 : W0;
            int H = l ? H1 : H0;
            float x = px * (float)W - 0.5f;
            float y = py * (float)H - 0.5f;
            float xf = floorf(x), yf = floorf(y);
            float fx = x - xf, fy = y - yf;
            int x0 = (int)xf, y0 = (int)yf;
            int x1 = x0 + 1, y1 = y0 + 1;
            bool vx0 = (x0 >= 0) & (x0 < W);
            bool vx1 = (x1 >= 0) & (x1 < W);
            bool vy0 = (y0 >= 0) & (y0 < H);
            bool vy1 = (y1 >= 0) & (y1 < H);
            int xc0 = min(max(x0, 0), W - 1);
            int xc1 = min(max(x1, 0), W - 1);
            int yc0 = min(max(y0, 0), H - 1);
            int yc1 = min(max(y1, 0), H - 1);
            int nb = n * H;
            int4 o;
            o.x = ((nb + yc0) * W + xc0) * 64;   // units: float4 (lvl0) / uint2 (lvl1)
            o.y = ((nb + yc0) * W + xc1) * 64;
            o.z = ((nb + yc1) * W + xc0) * 64;
            o.w = ((nb + yc1) * W + xc1) * 64;
            float4 w;
            w.x = (vx0 && vy0) ? (1.f - fx) * (1.f - fy) : 0.f;
            w.y = (vx1 && vy0) ? fx * (1.f - fy) : 0.f;
            w.z = (vx0 && vy1) ? (1.f - fx) * fy : 0.f;
            w.w = (vx1 && vy1) ? fx * fy : 0.f;
            if (l == 0) { soff0[pn] = o; swt0[pn] = w; }
            else        { soff1[pn] = o; swt1[pn] = w; }
        }
    }
    __syncthreads();

    const float4* const f0  = ((const float4*)fm0) + t;
    const uint2*  const f1h = g_fm1h + t;
    const int g = t >> 3;

    float4 acc = make_float4(0.f, 0.f, 0.f, 0.f);

    #pragma unroll 2
    for (int pn = 0; pn < NPN; ++pn) {
        // ---- level 0 (f32) ----
        {
            int4 o = soff0[pn];
            float4 w = swt0[pn];
            float gw = swg[pn * 16 + g];
            float4 v00 = __ldg(f0 + o.x);
            float4 v10 = __ldg(f0 + o.y);
            float4 v01 = __ldg(f0 + o.z);
            float4 v11 = __ldg(f0 + o.w);
            float wx = w.x * gw, wy = w.y * gw, wz = w.z * gw, ww = w.w * gw;
            acc.x += v00.x * wx + v10.x * wy + v01.x * wz + v11.x * ww;
            acc.y += v00.y * wx + v10.y * wy + v01.y * wz + v11.y * ww;
            acc.z += v00.z * wx + v10.z * wy + v01.z * wz + v11.z * ww;
            acc.w += v00.w * wx + v10.w * wy + v01.w * wz + v11.w * ww;
        }
        // ---- level 1 (fp16) ----
        {
            int4 o = soff1[pn];
            float4 w = swt1[pn];
            float gw = swg[pn * 16 + 8 + g];
            uint2 u00 = __ldg(f1h + o.x);
            uint2 u10 = __ldg(f1h + o.y);
            uint2 u01 = __ldg(f1h + o.z);
            uint2 u11 = __ldg(f1h + o.w);
            float wx = w.x * gw, wy = w.y * gw, wz = w.z * gw, ww = w.w * gw;
            float2 a0, a1;
            a0 = __half22float2(*reinterpret_cast<__half2*>(&u00.x));
            a1 = __half22float2(*reinterpret_cast<__half2*>(&u00.y));
            acc.x += a0.x * wx; acc.y += a0.y * wx; acc.z += a1.x * wx; acc.w += a1.y * wx;
            a0 = __half22float2(*reinterpret_cast<__half2*>(&u10.x));
            a1 = __half22float2(*reinterpret_cast<__half2*>(&u10.y));
            acc.x += a0.x * wy; acc.y += a0.y * wy; acc.z += a1.x * wy; acc.w += a1.y * wy;
            a0 = __half22float2(*reinterpret_cast<__half2*>(&u01.x));
            a1 = __half22float2(*reinterpret_cast<__half2*>(&u01.y));
            acc.x += a0.x * wz; acc.y += a0.y * wz; acc.z += a1.x * wz; acc.w += a1.y * wz;
            a0 = __half22float2(*reinterpret_cast<__half2*>(&u11.x));
            a1 = __half22float2(*reinterpret_cast<__half2*>(&u11.y));
            acc.x += a0.x * ww; acc.y += a0.y * ww; acc.z += a1.x * ww; acc.w += a1.y * ww;
        }
    }

    ((float4*)(g_acc + (size_t)a * CDIM))[t] = acc;
}

// ---------------------------------------------------------------------------
// K3: daf_small — levels 2,3 via smem tiles. 256 threads.
// Blocks [0, NB2): level 2, role (cam, channel-quarter q, anchor-chunk of 113)
// Blocks [NB2, NB2+NB3): level 3, role (cam, anchor-chunk of 36), full channels
// Partials written with plain stores to g_part2 / g_part3 (each elem once).
// ---------------------------------------------------------------------------
__global__ void __launch_bounds__(256, 1) daf_small_kernel(
    const float* __restrict__ fm2, const float* __restrict__ fm3,
    const float* __restrict__ pts, const float* __restrict__ wts)
{
    extern __shared__ float smem[];
    float*   tile  = smem;
    ushort4* s_off = (ushort4*)(smem + SM_OFF_F);
    float4*  s_w   = (float4*)(smem + SM_W_F);

    const int b = blockIdx.x;
    const int tid = threadIdx.x;
    const int warp = tid >> 5;
    const int lane = tid & 31;

    if (b < NB2) {
        // ---------------- level 2 ----------------
        const int cam = b / 32;
        const int r = b % 32;
        const int q = r >> 3;
        const int chunk = r & 7;
        const int a0 = chunk * L2_CHUNK;
        const int cnt = min(L2_CHUNK, A_TOT - a0);

        // tile load: 704 px x 64 ch (quarter q)
        {
            const float4* src = ((const float4*)fm2) + (size_t)(cam * 704) * 64 + q * 16;
            float4* t4 = (float4*)tile;
            #pragma unroll 4
            for (int i = tid; i < 704 * 16; i += 256) {
                int px = i >> 4, j = i & 15;
                t4[i] = __ldg(src + px * 64 + j);
            }
        }
        // params
        const int ns = cnt * P_PTS;
        for (int s = tid; s < ns; s += 256) {
            int al = s / P_PTS, p = s - al * P_PTS;
            int a = a0 + al;
            float2 pt = __ldg(((const float2*)pts) + ((a * P_PTS + p) * NCAMS + cam));
            float x = pt.x * (float)W2 - 0.5f;
            float y = pt.y * (float)H2 - 0.5f;
            float xf = floorf(x), yf = floorf(y);
            float fx = x - xf, fy = y - yf;
            int x0 = (int)xf, y0 = (int)yf;
            int x1 = x0 + 1, y1 = y0 + 1;
            bool vx0 = (x0 >= 0) & (x0 < W2);
            bool vx1 = (x1 >= 0) & (x1 < W2);
            bool vy0 = (y0 >= 0) & (y0 < H2);
            bool vy1 = (y1 >= 0) & (y1 < H2);
            int xc0 = min(max(x0, 0), W2 - 1);
            int xc1 = min(max(x1, 0), W2 - 1);
            int yc0 = min(max(y0, 0), H2 - 1);
            int yc1 = min(max(y1, 0), H2 - 1);
            s_off[s] = make_ushort4((unsigned short)(yc0 * W2 + xc0),
                                    (unsigned short)(yc0 * W2 + xc1),
                                    (unsigned short)(yc1 * W2 + xc0),
                                    (unsigned short)(yc1 * W2 + xc1));
            float4 w;
            w.x = (vx0 && vy0) ? (1.f - fx) * (1.f - fy) : 0.f;
            w.y = (vx1 && vy0) ? fx * (1.f - fy) : 0.f;
            w.z = (vx0 && vy1) ? (1.f - fx) * fy : 0.f;
            w.w = (vx1 && vy1) ? fx * fy : 0.f;
            s_w[s] = w;
        }
        __syncthreads();

        // gather: warp per anchor, lane covers 2 channels of the 64-ch quarter
        const int lane2 = lane * 2;
        const int gsub = q * 2 + (lane >> 4);   // group of this lane's channels
        for (int al = warp; al < cnt; al += 8) {
            int a = a0 + al;
            float ax = 0.f, ay = 0.f;
            #pragma unroll
            for (int p = 0; p < P_PTS; ++p) {
                int s = al * P_PTS + p;
                ushort4 o = s_off[s];
                float4 wt = s_w[s];
                float gw = __ldg(wts + (size_t)((a * P_PTS + p) * NCAMS + cam) * 32 + 16 + gsub);
                float c0 = wt.x * gw, c1 = wt.y * gw, c2 = wt.z * gw, c3 = wt.w * gw;
                float2 v0 = *(const float2*)(tile + o.x * 64 + lane2);
                float2 v1 = *(const float2*)(tile + o.y * 64 + lane2);
                float2 v2 = *(const float2*)(tile + o.z * 64 + lane2);
                float2 v3 = *(const float2*)(tile + o.w * 64 + lane2);
                ax += v0.x * c0 + v1.x * c1 + v2.x * c2 + v3.x * c3;
                ay += v0.y * c0 + v1.y * c1 + v2.y * c2 + v3.y * c3;
            }
            *(float2*)(g_part2 + ((size_t)cam * A_TOT + a) * CDIM + q * 64 + lane2) =
                make_float2(ax, ay);
        }
    } else {
        // ---------------- level 3 ----------------
        const int b2 = b - NB2;
        const int cam = b2 / L3_NCHUNK;
        const int chunk = b2 % L3_NCHUNK;
        const int a0 = chunk * L3_CHUNK;

        // tile load: contiguous 176 px x 256 ch
        {
            const float4* src = ((const float4*)fm3) + (size_t)(cam * 176) * 64;
            float4* t4 = (float4*)tile;
            #pragma unroll 4
            for (int i = tid; i < 176 * 64; i += 256) t4[i] = __ldg(src + i);
        }
        // params
        for (int s = tid; s < L3_CHUNK * P_PTS; s += 256) {
            int al = s / P_PTS, p = s - al * P_PTS;
            int a = a0 + al;
            float2 pt = __ldg(((const float2*)pts) + ((a * P_PTS + p) * NCAMS + cam));
            float x = pt.x * (float)W3 - 0.5f;
            float y = pt.y * (float)H3 - 0.5f;
            float xf = floorf(x), yf = floorf(y);
            float fx = x - xf, fy = y - yf;
            int x0 = (int)xf, y0 = (int)yf;
            int x1 = x0 + 1, y1 = y0 + 1;
            bool vx0 = (x0 >= 0) & (x0 < W3);
            bool vx1 = (x1 >= 0) & (x1 < W3);
            bool vy0 = (y0 >= 0) & (y0 < H3);
            bool vy1 = (y1 >= 0) & (y1 < H3);
            int xc0 = min(max(x0, 0), W3 - 1);
            int xc1 = min(max(x1, 0), W3 - 1);
            int yc0 = min(max(y0, 0), H3 - 1);
            int yc1 = min(max(y1, 0), H3 - 1);
            s_off[s] = make_ushort4((unsigned short)(yc0 * W3 + xc0),
                                    (unsigned short)(yc0 * W3 + xc1),
                                    (unsigned short)(yc1 * W3 + xc0),
                                    (unsigned short)(yc1 * W3 + xc1));
            float4 w;
            w.x = (vx0 && vy0) ? (1.f - fx) * (1.f - fy) : 0.f;
            w.y = (vx1 && vy0) ? fx * (1.f - fy) : 0.f;
            w.z = (vx0 && vy1) ? (1.f - fx) * fy : 0.f;
            w.w = (vx1 && vy1) ? fx * fy : 0.f;
            s_w[s] = w;
        }
        __syncthreads();

        // gather: warp per anchor; lane covers ch [4l,4l+4) and [128+4l, 128+4l+4)
        const int lane4 = lane * 4;
        const int gl = lane >> 3;
        for (int al = warp; al < L3_CHUNK; al += 8) {
            int a = a0 + al;
            float4 accl = make_float4(0.f, 0.f, 0.f, 0.f);
            float4 acch = make_float4(0.f, 0.f, 0.f, 0.f);
            #pragma unroll
            for (int p = 0; p < P_PTS; ++p) {
                int s = al * P_PTS + p;
                ushort4 o = s_off[s];
                float4 wt = s_w[s];
                size_t wbase = (size_t)((a * P_PTS + p) * NCAMS + cam) * 32 + 24;
                float gwl = __ldg(wts + wbase + gl);
                float gwh = __ldg(wts + wbase + 4 + gl);
                #pragma unroll
                for (int k = 0; k < 4; ++k) {
                    int pix = (k == 0) ? o.x : (k == 1) ? o.y : (k == 2) ? o.z : o.w;
                    float wk = (k == 0) ? wt.x : (k == 1) ? wt.y : (k == 2) ? wt.z : wt.w;
                    const float* base = tile + pix * 256 + lane4;
                    float4 vl = *(const float4*)base;
                    float4 vh = *(const float4*)(base + 128);
                    float cl = wk * gwl, ch = wk * gwh;
                    accl.x += vl.x * cl; accl.y += vl.y * cl;
                    accl.z += vl.z * cl; accl.w += vl.w * cl;
                    acch.x += vh.x * ch; acch.y += vh.y * ch;
                    acch.z += vh.z * ch; acch.w += vh.w * ch;
                }
            }
            float* dst = g_part3 + ((size_t)cam * A_TOT + a) * CDIM + lane4;
            *(float4*)dst = accl;
            *(float4*)(dst + 128) = acch;
        }
    }
}

// ---------------------------------------------------------------------------
// K4: proj — reduce 13 partial sources, K-chunked GEMM, atomicAdd epilogue.
// Grid: 150 anchor-groups x 4 K-chunks = 600 blocks; 256 threads (one out ch).
// ---------------------------------------------------------------------------
#define APB 6
__global__ void __launch_bounds__(256) proj_kernel(
    const float* __restrict__ wproj, float* __restrict__ out)
{
    __shared__ float sacc[APB][64];
    const int b = blockIdx.x;
    const int kq = b & 3;
    const int a0 = (b >> 2) * APB;
    const int k0 = kq * 64;
    const int c = threadIdx.x;

    // stage acc chunk = g_acc + sum of 12 per-cam partials
    for (int i = c; i < APB * 64; i += 256) {
        int ai = i >> 6, kk = i & 63;
        size_t a = a0 + ai;
        size_t k = k0 + kk;
        float v = g_acc[a * CDIM + k];
        #pragma unroll
        for (int cam = 0; cam < NCAMS; ++cam) {
            v += g_part2[((size_t)cam * A_TOT + a) * CDIM + k];
            v += g_part3[((size_t)cam * A_TOT + a) * CDIM + k];
        }
        sacc[ai][kk] = v;
    }
    __syncthreads();

    float r[APB];
    #pragma unroll
    for (int a = 0; a < APB; ++a) r[a] = 0.f;

    #pragma unroll 8
    for (int kk = 0; kk < 64; ++kk) {
        float wv = __ldg(wproj + (size_t)(k0 + kk) * CDIM + c);
        #pragma unroll
        for (int a = 0; a < APB; ++a) r[a] += sacc[a][kk] * wv;
    }

    #pragma unroll
    for (int a = 0; a < APB; ++a)
        atomicAdd(out + (size_t)(a0 + a) * 512 + c, r[a]);
}

// ---------------------------------------------------------------------------
extern "C" void kernel_launch(void* const* d_in, const int* in_sizes, int n_in,
                              void* d_out, int out_size)
{
    const float* fm0   = (const float*)d_in[0];
    const float* fm1   = (const float*)d_in[1];
    const float* fm2   = (const float*)d_in[2];
    const float* fm3   = (const float*)d_in[3];
    const float* pts   = (const float*)d_in[4];
    const float* wts   = (const float*)d_in[5];
    const float* inst  = (const float*)d_in[6];
    const float* wproj = (const float*)d_in[7];
    const float* bproj = (const float*)d_in[8];
    float* out = (float*)d_out;

    cudaFuncSetAttribute(daf_small_kernel,
                         cudaFuncAttributeMaxDynamicSharedMemorySize, SMEM_SMALL);

    prep_kernel<<<CONV_BLKS + A_TOT, 256>>>(fm1, inst, bproj, out);
    daf_big_kernel<<<A_TOT, 64>>>(fm0, pts, wts);
    daf_small_kernel<<<NB2 + NB3, 256, SMEM_SMALL>>>(fm2, fm3, pts, wts);
    proj_kernel<<<(A_TOT / APB) * 4, 256>>>(wproj, out);
}

// round 3
// speedup vs baseline: 1.5093x; 1.5093x over previous
#include <cuda_runtime.h>
#include <cuda_fp16.h>

// ---------------------------------------------------------------- constants
#define A_TOT 900
#define P_PTS 13
#define NCAMS 6
#define CDIM  256
#define NPN   (P_PTS * NCAMS)        // 78 (p-major, cam inner)

#define W0 176
#define H0 64
#define W1 88
#define H1 32
#define W2 44
#define H2 16
#define W3 22
#define H3 8

// fp16 scratch for levels 1..3, uint2 = 4 halves. Per pixel: 256ch*2B = 64 uint2.
#define L1_U2 1081344                 // 6*32*88 px * 64
#define L2_U2 270336                  // 6*16*44 px * 64
#define L3_U2 67584                   // 6*8*22  px * 64
#define L2_BASE L1_U2
#define L3_BASE (L1_U2 + L2_U2)
#define FMH_U2  (L1_U2 + L2_U2 + L3_U2)

#define CONV1_BLK (L1_U2 / 256)       // 4224
#define CONV2_BLK (L2_U2 / 256)       // 1056
#define CONV3_BLK (L3_U2 / 256)       // 264
#define PREP_BLKS (CONV1_BLK + CONV2_BLK + CONV3_BLK + A_TOT)

__device__ float g_acc[A_TOT * CDIM];
__device__ uint2 g_fmh[FMH_U2];

// ---------------------------------------------------------------------------
// K1: prep. Convert fm1/fm2/fm3 -> fp16 scratch; init out = [bias | instance].
// ---------------------------------------------------------------------------
__global__ void __launch_bounds__(256) prep_kernel(
    const float* __restrict__ fm1, const float* __restrict__ fm2,
    const float* __restrict__ fm3, const float* __restrict__ inst,
    const float* __restrict__ bproj, float* __restrict__ out)
{
    const int b = blockIdx.x;
    const int t = threadIdx.x;
    const float* src = nullptr;
    int i = 0, base = 0;
    if (b < CONV1_BLK) {
        src = fm1; i = b * 256 + t; base = 0;
    } else if (b < CONV1_BLK + CONV2_BLK) {
        src = fm2; i = (b - CONV1_BLK) * 256 + t; base = L2_BASE;
    } else if (b < CONV1_BLK + CONV2_BLK + CONV3_BLK) {
        src = fm3; i = (b - CONV1_BLK - CONV2_BLK) * 256 + t; base = L3_BASE;
    } else {
        int a = b - (CONV1_BLK + CONV2_BLK + CONV3_BLK);
        out[(size_t)a * 512 + t]       = __ldg(bproj + t);
        out[(size_t)a * 512 + 256 + t] = __ldg(inst + (size_t)a * 256 + t);
        return;
    }
    float4 f = __ldg(((const float4*)src) + i);
    __half2 h0 = __floats2half2_rn(f.x, f.y);
    __half2 h1 = __floats2half2_rn(f.z, f.w);
    uint2 u;
    u.x = *reinterpret_cast<unsigned*>(&h0);
    u.y = *reinterpret_cast<unsigned*>(&h1);
    g_fmh[base + i] = u;
}

// ---------------------------------------------------------------------------
// K2: daf — all 4 levels, one block per anchor, 64 threads.
// Level 0: f32 float4 gather. Levels 1-3: fp16 uint2 gather from g_fmh
// (level base folded into precomputed offsets).
// ---------------------------------------------------------------------------
__global__ void __launch_bounds__(64) daf_kernel(
    const float* __restrict__ fm0, const float* __restrict__ pts,
    const float* __restrict__ wts)
{
    __shared__ int4   soff0[NPN];
    __shared__ float4 swt0[NPN];
    __shared__ int4   soffH[NPN * 3];
    __shared__ float4 swtH[NPN * 3];
    __shared__ float  swg[NPN * 32];   // full per-pn weight record [l][g]

    const int a = blockIdx.x;
    const int t = threadIdx.x;

    // stage group weights: 78 * 32 floats = 624 float4, contiguous
    {
        const float4* wsrc = (const float4*)(wts + (size_t)a * NPN * 32);
        float4* wdst = (float4*)swg;
        #pragma unroll
        for (int i = t; i < NPN * 8; i += 64) wdst[i] = __ldg(wsrc + i);
    }

    // per-sample bilinear precompute for all 4 levels
    {
        const float* pbase = pts + (size_t)a * NPN * 2;
        const int Ws[4] = {W0, W1, W2, W3};
        const int Hs[4] = {H0, H1, H2, H3};
        const int Bs[4] = {0, 0, L2_BASE, L3_BASE};
        for (int s = t; s < NPN * 4; s += 64) {
            int pn = s >> 2, l = s & 3;
            int n = pn % NCAMS;
            float px = __ldg(pbase + pn * 2 + 0);
            float py = __ldg(pbase + pn * 2 + 1);
            int W = Ws[l], H = Hs[l];
            float x = px * (float)W - 0.5f;
            float y = py * (float)H - 0.5f;
            float xf = floorf(x), yf = floorf(y);
            float fx = x - xf, fy = y - yf;
            int x0 = (int)xf, y0 = (int)yf;
            int x1 = x0 + 1, y1 = y0 + 1;
            bool vx0 = (x0 >= 0) & (x0 < W);
            bool vx1 = (x1 >= 0) & (x1 < W);
            bool vy0 = (y0 >= 0) & (y0 < H);
            bool vy1 = (y1 >= 0) & (y1 < H);
            int xc0 = min(max(x0, 0), W - 1);
            int xc1 = min(max(x1, 0), W - 1);
            int yc0 = min(max(y0, 0), H - 1);
            int yc1 = min(max(y1, 0), H - 1);
            int nb = n * H;
            int base = Bs[l];
            int4 o;   // units: float4 (lvl0) / uint2 (lvl1-3); both 64 per pixel
            o.x = base + ((nb + yc0) * W + xc0) * 64;
            o.y = base + ((nb + yc0) * W + xc1) * 64;
            o.z = base + ((nb + yc1) * W + xc0) * 64;
            o.w = base + ((nb + yc1) * W + xc1) * 64;
            float4 w;
            w.x = (vx0 && vy0) ? (1.f - fx) * (1.f - fy) : 0.f;
            w.y = (vx1 && vy0) ? fx * (1.f - fy) : 0.f;
            w.z = (vx0 && vy1) ? (1.f - fx) * fy : 0.f;
            w.w = (vx1 && vy1) ? fx * fy : 0.f;
            if (l == 0) { soff0[pn] = o; swt0[pn] = w; }
            else        { soffH[pn * 3 + (l - 1)] = o; swtH[pn * 3 + (l - 1)] = w; }
        }
    }
    __syncthreads();

    const float4* const f0 = ((const float4*)fm0) + t;
    const uint2*  const fh = g_fmh + t;
    const int g = t >> 3;

    float4 acc = make_float4(0.f, 0.f, 0.f, 0.f);

    #pragma unroll 2
    for (int pn = 0; pn < NPN; ++pn) {
        // ---- level 0 (f32) ----
        {
            int4 o = soff0[pn];
            float4 w = swt0[pn];
            float gw = swg[pn * 32 + g];
            float4 v00 = __ldg(f0 + o.x);
            float4 v10 = __ldg(f0 + o.y);
            float4 v01 = __ldg(f0 + o.z);
            float4 v11 = __ldg(f0 + o.w);
            float wx = w.x * gw, wy = w.y * gw, wz = w.z * gw, ww = w.w * gw;
            acc.x += v00.x * wx + v10.x * wy + v01.x * wz + v11.x * ww;
            acc.y += v00.y * wx + v10.y * wy + v01.y * wz + v11.y * ww;
            acc.z += v00.z * wx + v10.z * wy + v01.z * wz + v11.z * ww;
            acc.w += v00.w * wx + v10.w * wy + v01.w * wz + v11.w * ww;
        }
        // ---- levels 1..3 (fp16) ----
        #pragma unroll
        for (int lv = 0; lv < 3; ++lv) {
            int4 o = soffH[pn * 3 + lv];
            float4 w = swtH[pn * 3 + lv];
            float gw = swg[pn * 32 + (lv + 1) * 8 + g];
            uint2 u00 = __ldg(fh + o.x);
            uint2 u10 = __ldg(fh + o.y);
            uint2 u01 = __ldg(fh + o.z);
            uint2 u11 = __ldg(fh + o.w);
            float wx = w.x * gw, wy = w.y * gw, wz = w.z * gw, ww = w.w * gw;
            float2 a0, a1;
            a0 = __half22float2(*reinterpret_cast<__half2*>(&u00.x));
            a1 = __half22float2(*reinterpret_cast<__half2*>(&u00.y));
            acc.x += a0.x * wx; acc.y += a0.y * wx; acc.z += a1.x * wx; acc.w += a1.y * wx;
            a0 = __half22float2(*reinterpret_cast<__half2*>(&u10.x));
            a1 = __half22float2(*reinterpret_cast<__half2*>(&u10.y));
            acc.x += a0.x * wy; acc.y += a0.y * wy; acc.z += a1.x * wy; acc.w += a1.y * wy;
            a0 = __half22float2(*reinterpret_cast<__half2*>(&u01.x));
            a1 = __half22float2(*reinterpret_cast<__half2*>(&u01.y));
            acc.x += a0.x * wz; acc.y += a0.y * wz; acc.z += a1.x * wz; acc.w += a1.y * wz;
            a0 = __half22float2(*reinterpret_cast<__half2*>(&u11.x));
            a1 = __half22float2(*reinterpret_cast<__half2*>(&u11.y));
            acc.x += a0.x * ww; acc.y += a0.y * ww; acc.z += a1.x * ww; acc.w += a1.y * ww;
        }
    }

    ((float4*)(g_acc + (size_t)a * CDIM))[t] = acc;
}

// ---------------------------------------------------------------------------
// K3: proj — 8 K-chunks of 32, 150 anchor-groups of 6 -> 1200 blocks.
// atomicAdd into out (pre-initialized with bias by prep).
// ---------------------------------------------------------------------------
#define APB 6
__global__ void __launch_bounds__(256) proj_kernel(
    const float* __restrict__ wproj, float* __restrict__ out)
{
    __shared__ float sacc[APB][32];
    const int b = blockIdx.x;
    const int kq = b & 7;
    const int a0 = (b >> 3) * APB;
    const int k0 = kq * 32;
    const int c = threadIdx.x;

    if (c < APB * 32) {
        int ai = c >> 5, kk = c & 31;
        sacc[ai][kk] = g_acc[(size_t)(a0 + ai) * CDIM + k0 + kk];
    }
    __syncthreads();

    float r[APB];
    #pragma unroll
    for (int a = 0; a < APB; ++a) r[a] = 0.f;

    #pragma unroll 8
    for (int kk = 0; kk < 32; ++kk) {
        float wv = __ldg(wproj + (size_t)(k0 + kk) * CDIM + c);
        #pragma unroll
        for (int a = 0; a < APB; ++a) r[a] += sacc[a][kk] * wv;
    }

    #pragma unroll
    for (int a = 0; a < APB; ++a)
        atomicAdd(out + (size_t)(a0 + a) * 512 + c, r[a]);
}

// ---------------------------------------------------------------------------
extern "C" void kernel_launch(void* const* d_in, const int* in_sizes, int n_in,
                              void* d_out, int out_size)
{
    const float* fm0   = (const float*)d_in[0];
    const float* fm1   = (const float*)d_in[1];
    const float* fm2   = (const float*)d_in[2];
    const float* fm3   = (const float*)d_in[3];
    const float* pts   = (const float*)d_in[4];
    const float* wts   = (const float*)d_in[5];
    const float* inst  = (const float*)d_in[6];
    const float* wproj = (const float*)d_in[7];
    const float* bproj = (const float*)d_in[8];
    float* out = (float*)d_out;

    prep_kernel<<<PREP_BLKS, 256>>>(fm1, fm2, fm3, inst, bproj, out);
    daf_kernel<<<A_TOT, 64>>>(fm0, pts, wts);
    proj_kernel<<<(A_TOT / APB) * 8, 256>>>(wproj, out);
}